// round 10
// baseline (speedup 1.0000x reference)
#include <cuda_runtime.h>
#include <cstdint>

#define BATCH 8
#define NPTS  8192
#define CFEAT 64
#define SPTS  1024      // NPOINT
#define KS    32        // NSAMPLE
#define CIN0  67        // 3 + CFEAT
#define O0    64
#define O1    64
#define O2    128
#define MTOT  (BATCH*SPTS*KS)   // 262144
#define NPART (MTOT/128)        // 2048 per-warp stat partials
#define TRB   280               // persistent transpose CTAs in the fps launch
#define NSEG  (BATCH*SPTS)      // 8192 pooled segments
#define POOL_OFF ((size_t)O2*NSEG)

// ---------------- scratch (static device globals; no allocations) ----------
__device__ __align__(128) float g_scratch[(size_t)(CIN0 + O0 + O1 + O2) * MTOT];
__device__ __align__(128) float g_featT[(size_t)BATCH * NPTS * CFEAT];
__device__ __align__(128) float g_part[(size_t)NPART * O2 * 2];
__device__ __align__(128) int   g_idx[BATCH * SPTS * KS];
__device__ __align__(128) float g_aff[3 * 256];   // per layer: a[0..127], b'[128..255]

// ----------------------------- f32x2 helpers -------------------------------
typedef unsigned long long ull;
__device__ __forceinline__ ull pk2(float lo, float hi) {
    ull r; asm("mov.b64 %0, {%1,%2};" : "=l"(r) : "f"(lo), "f"(hi)); return r;
}
__device__ __forceinline__ void upk2(ull v, float& lo, float& hi) {
    asm("mov.b64 {%0,%1}, %2;" : "=f"(lo), "=f"(hi) : "l"(v));
}
__device__ __forceinline__ ull add2(ull a, ull b) {
    ull r; asm("add.rn.f32x2 %0, %1, %2;" : "=l"(r) : "l"(a), "l"(b)); return r;
}
__device__ __forceinline__ ull mul2(ull a, ull b) {
    ull r; asm("mul.rn.f32x2 %0, %1, %2;" : "=l"(r) : "l"(a), "l"(b)); return r;
}
__device__ __forceinline__ ull fma2(ull a, ull b, ull c) {
    ull r; asm("fma.rn.f32x2 %0, %1, %2, %3;" : "=l"(r) : "l"(a), "l"(b), "l"(c)); return r;
}

// dummy kernels to align the ncu capture window onto the fused fps kernel
__global__ void dummy_kernel() {}

// ---------------------------------------------------------------------------
// 1) FPS (blocks 0..7): 512 threads, 16 pts/thread, R9-proven 2-barrier tail
//    (deferred gated candidate scan, atomicMin, uint4 block-max).
//    Blocks 8.. run a persistent feature transpose.
// ---------------------------------------------------------------------------
#define FPT 16          // points per thread
#define FTH 512         // threads
#define FWP (FTH/32)    // 16 warps

__global__ __launch_bounds__(FTH, 1) void fps_tr_kernel(const float* __restrict__ xyz,
                                                        const float* __restrict__ feat,
                                                        float* __restrict__ out_xyz,
                                                        float* __restrict__ featT)
{
    const int t = threadIdx.x;

    if (blockIdx.x >= BATCH) {
        // ------- persistent transpose: feat[B][C][N] -> featT[B][N][C] -----
        __shared__ float tile[64][33];
        const int wid = t >> 5, lane = t & 31;
        for (int blk = (int)blockIdx.x - BATCH; blk < BATCH * (NPTS / 32); blk += TRB) {
            const int b  = blk >> 8;
            const int n0 = (blk & 255) * 32;
            const float* src = feat + (size_t)b * CFEAT * NPTS + n0;
#pragma unroll
            for (int r = 0; r < 4; r++) {
                const int c = r * 16 + wid;
                tile[c][lane] = src[(size_t)c * NPTS + lane];
            }
            __syncthreads();
            const int c  = t & 63;
            const int ns = t >> 6;
            float* dst = featT + ((size_t)b * NPTS + n0) * 64 + c;
#pragma unroll
            for (int j = 0; j < 4; j++) {
                const int n = ns + j * 8;
                dst[(size_t)n * 64] = tile[c][n];
            }
            __syncthreads();
        }
        return;
    }

    // ---------------- FPS branch ----------------
    extern __shared__ float sm[];
    float* sx = sm;
    float* sy = sm + NPTS;
    float* sz = sm + 2 * NPTS;
    __shared__ __align__(16) unsigned s_wv[FWP];
    __shared__ int s_cand[2];

    const int b = blockIdx.x;
    const int lane = t & 31, wid = t >> 5;
    const float* base = xyz + (size_t)b * NPTS * 3;

    for (int j = t; j < NPTS; j += FTH) {
        sx[j] = base[3 * j + 0];
        sy[j] = base[3 * j + 1];
        sz[j] = base[3 * j + 2];
    }
    if (t == 0) { s_cand[0] = 0x7fffffff; s_cand[1] = 0x7fffffff; }
    __syncthreads();

    const int i0 = t * FPT;
    ull px2[FPT / 2], py2[FPT / 2], pz2[FPT / 2];
    float dist[FPT];
#pragma unroll
    for (int i = 0; i < FPT / 2; i++) {
        px2[i] = pk2(sx[i0 + 2 * i], sx[i0 + 2 * i + 1]);
        py2[i] = pk2(sy[i0 + 2 * i], sy[i0 + 2 * i + 1]);
        pz2[i] = pk2(sz[i0 + 2 * i], sz[i0 + 2 * i + 1]);
    }
#pragma unroll
    for (int i = 0; i < FPT; i++) dist[i] = 1e10f;

    int far = 0;
    for (int it = 0; it < SPTS; ++it) {
        const float cx = sx[far], cy = sy[far], cz = sz[far];
        if (t == 0) {
            float* o = out_xyz + ((size_t)b * SPTS + it) * 3;
            o[0] = cx; o[1] = cy; o[2] = cz;
        }
        const ull ncx = pk2(-cx, -cx), ncy = pk2(-cy, -cy), ncz = pk2(-cz, -cz);
        float bv0 = 0.0f, bv1 = 0.0f;    // dists >= 0, 0 is identity; split chains
#pragma unroll
        for (int i = 0; i < FPT / 2; i++) {
            const ull dx = add2(px2[i], ncx);
            const ull dy = add2(py2[i], ncy);
            const ull dz = add2(pz2[i], ncz);
            ull tt = mul2(dx, dx);
            tt = fma2(dy, dy, tt);
            tt = fma2(dz, dz, tt);          // same per-lane rounding/assoc as scalar FMA form
            float d0, d1; upk2(tt, d0, d1); // free: register-pair aliasing
            const float n0 = fminf(dist[2 * i],     d0);
            const float n1 = fminf(dist[2 * i + 1], d1);
            dist[2 * i] = n0; dist[2 * i + 1] = n1;
            bv0 = fmaxf(bv0, n0);
            bv1 = fmaxf(bv1, n1);
        }
        const float bv = fmaxf(bv0, bv1);
        const unsigned key = __float_as_uint(bv);           // bv >= 0 -> monotonic as uint
        const unsigned wmx = __reduce_max_sync(0xffffffffu, key);
        if (lane == 0) s_wv[wid] = wmx;
        __syncthreads();                                    // barrier 1

        const uint4* wv = (const uint4*)s_wv;               // vectorized 16-slot block max
        const uint4 a0 = wv[0], a1 = wv[1], a2 = wv[2], a3 = wv[3];
        const unsigned bmx = max(max(max(max(a0.x, a0.y), max(a0.z, a0.w)),
                                     max(max(a1.x, a1.y), max(a1.z, a1.w))),
                                 max(max(max(a2.x, a2.y), max(a2.z, a2.w)),
                                     max(max(a3.x, a3.y), max(a3.z, a3.w))));

        const int p = it & 1;
        if (key == bmx) {                                   // candidate thread(s) only
            int nidx = 0x7fffffff;                          // branchless lowest-match scan
#pragma unroll
            for (int i = 0; i < FPT; i++)
                if (__float_as_uint(dist[i]) == bmx) nidx = min(nidx, i0 + i);
            atomicMin(&s_cand[p], nidx);                    // lowest global index on tie
        }
        if (t == 0) s_cand[1 - p] = 0x7fffffff;             // reset other slot (safe: after bar1)
        __syncthreads();                                    // barrier 2
        far = s_cand[p];
    }
}

// ---------------------------------------------------------------------------
// 2) Ball query: one warp per centroid; ballot-prefix compaction, early exit.
// ---------------------------------------------------------------------------
__global__ __launch_bounds__(256) void ballquery_kernel(const float* __restrict__ xyz,
                                                        const float* __restrict__ new_xyz,
                                                        int* __restrict__ idx)
{
    const int warpg = blockIdx.x * 8 + (threadIdx.x >> 5);
    const int lane  = threadIdx.x & 31;
    const int b = warpg >> 10;
    const int s = warpg & 1023;

    const float* nx = new_xyz + ((size_t)b * SPTS + s) * 3;
    const float cx = nx[0], cy = nx[1], cz = nx[2];
    const float* base = xyz + (size_t)b * NPTS * 3;
    int* out = idx + (size_t)(b * SPTS + s) * KS;
    const float R2 = 0.04f;

    int cnt = 0, first = -1;
    for (int j0 = 0; j0 < NPTS; j0 += 32) {
        const int j = j0 + lane;
        float dx = base[3 * j + 0] - cx;
        float dy = base[3 * j + 1] - cy;
        float dz = base[3 * j + 2] - cz;
        float d = dx * dx + dy * dy + dz * dz;
        bool in = (d <= R2);
        unsigned bal = __ballot_sync(0xffffffffu, in);
        if (first < 0 && bal) first = j0 + __ffs(bal) - 1;
        int pos = cnt + __popc(bal & ((1u << lane) - 1u));
        if (in && pos < KS) out[pos] = j;
        cnt += __popc(bal);
        if (cnt >= KS) break;
    }
    for (int p = cnt + lane; p < KS; p += 32) out[p] = first;
}

// ---------------------------------------------------------------------------
// 3) Grouping: build X0[c][m], m=(b*S+s)*K+k; contiguous 256B feature rows.
// ---------------------------------------------------------------------------
__global__ __launch_bounds__(256) void group_kernel(const float* __restrict__ xyz,
                                                    const float* __restrict__ featT,
                                                    const float* __restrict__ new_xyz,
                                                    const int* __restrict__ idx,
                                                    float* __restrict__ X)
{
    const int m = blockIdx.x * 256 + threadIdx.x;
    const int b = m >> 15;
    const int s = (m >> 5) & 1023;
    const int i = idx[m];

    const float* p  = xyz + ((size_t)b * NPTS + i) * 3;
    const float* nx = new_xyz + ((size_t)b * SPTS + s) * 3;
    X[0 * (size_t)MTOT + m] = p[0] - nx[0];
    X[1 * (size_t)MTOT + m] = p[1] - nx[1];
    X[2 * (size_t)MTOT + m] = p[2] - nx[2];

    const float4* f = (const float4*)(featT + ((size_t)b * NPTS + i) * 64);
#pragma unroll
    for (int j = 0; j < 16; j++) {
        const float4 v = f[j];
        X[(size_t)(3 + 4 * j + 0) * MTOT + m] = v.x;
        X[(size_t)(3 + 4 * j + 1) * MTOT + m] = v.y;
        X[(size_t)(3 + 4 * j + 2) * MTOT + m] = v.z;
        X[(size_t)(3 + 4 * j + 3) * MTOT + m] = v.w;
    }
}

// ---------------------------------------------------------------------------
// 4) GEMM: Y[o][m] = sum_c W[o][c] * relu?(a_c x + b'_c) + bias[o]
//    Tile 16(o) x 4(m)/thread, 2 CTAs/SM, depth-2 x prefetch, fused stats.
//    POOL variant: never writes Y; emits per-(o,seg) pooled max AND min
//    (exact: fmaf monotone in y, so BN+relu+maxpool commutes via sign(a)).
// ---------------------------------------------------------------------------
template <int CIN, int OUT, bool TR, bool POOL>
__global__ __launch_bounds__(256, 2) void gemm_kernel(const float* __restrict__ Xin,
                                                      const float* __restrict__ W,
                                                      const float* __restrict__ bias,
                                                      const float* __restrict__ aff,
                                                      float* __restrict__ Y,
                                                      float* __restrict__ pool,
                                                      float* __restrict__ part)
{
    __shared__ float sW[CIN * OUT];
    __shared__ float sA[TR ? CIN : 1];
    __shared__ float sB[TR ? CIN : 1];

    const int t = threadIdx.x;
    for (int i = t; i < CIN * OUT; i += 256) {
        const int c = i / OUT, o = i % OUT;
        sW[i] = W[o * CIN + c];            // transpose: sW[c][o]
    }
    if (TR) {
        for (int c = t; c < CIN; c += 256) { sA[c] = aff[c]; sB[c] = aff[128 + c]; }
    }
    __syncthreads();

    constexpr int OC   = OUT / 16;          // o-chunks per block
    constexpr int MW   = 8 / OC;            // m-warps per block
    constexpr int MBLK = MW * 128;
    const int warp = t >> 5, lane = t & 31;
    const int ow = warp % OC, mw = warp / OC;
    const int m0 = blockIdx.x * MBLK + mw * 128 + lane * 4;
    const int o0 = ow * 16;

    float acc[16][4];
#pragma unroll
    for (int oo = 0; oo < 16; oo++) {
        const float bv = bias[o0 + oo];
#pragma unroll
        for (int mm = 0; mm < 4; mm++) acc[oo][mm] = bv;
    }

    const float* xp = Xin + m0;
    float4 xv = *(const float4*)(xp);
    float4 xn = *(const float4*)(xp + (size_t)MTOT);

#pragma unroll 4
    for (int c = 0; c < CIN; c++) {
        const float4 xf = xv;
        xv = xn;
        if (c + 2 < CIN) xn = *(const float4*)(xp + (size_t)(c + 2) * MTOT);

        float xs[4] = {xf.x, xf.y, xf.z, xf.w};
        if (TR) {
            const float a = sA[c], bb = sB[c];
#pragma unroll
            for (int mm = 0; mm < 4; mm++) xs[mm] = fmaxf(fmaf(a, xs[mm], bb), 0.0f);
        }
        const float4* wp = (const float4*)(sW + c * OUT + o0);
        const float4 w0 = wp[0], w1 = wp[1], w2 = wp[2], w3 = wp[3];
        const float ws[16] = {w0.x, w0.y, w0.z, w0.w, w1.x, w1.y, w1.z, w1.w,
                              w2.x, w2.y, w2.z, w2.w, w3.x, w3.y, w3.z, w3.w};
#pragma unroll
        for (int oo = 0; oo < 16; oo++)
#pragma unroll
            for (int mm = 0; mm < 4; mm++)
                acc[oo][mm] = fmaf(ws[oo], xs[mm], acc[oo][mm]);
    }

    const int pidx = blockIdx.x * MW + mw;   // 0..NPART-1 (each warp owns 128 m)
#pragma unroll
    for (int oo = 0; oo < 16; oo++) {
        if (!POOL) {
            float* yp = Y + (size_t)(o0 + oo) * MTOT + m0;
            *(float4*)yp = make_float4(acc[oo][0], acc[oo][1], acc[oo][2], acc[oo][3]);
        }

        float s = (acc[oo][0] + acc[oo][1]) + (acc[oo][2] + acc[oo][3]);
        float q = fmaf(acc[oo][0], acc[oo][0], fmaf(acc[oo][1], acc[oo][1],
                  fmaf(acc[oo][2], acc[oo][2], acc[oo][3] * acc[oo][3])));
#pragma unroll
        for (int d = 16; d > 0; d >>= 1) {
            s += __shfl_down_sync(0xffffffffu, s, d);
            q += __shfl_down_sync(0xffffffffu, q, d);
        }
        if (lane == 0) {
            float* pp = part + ((size_t)pidx * OUT + (o0 + oo)) * 2;
            pp[0] = s; pp[1] = q;
        }

        if (POOL) {
            float mx = fmaxf(fmaxf(acc[oo][0], acc[oo][1]), fmaxf(acc[oo][2], acc[oo][3]));
            float mn = fminf(fminf(acc[oo][0], acc[oo][1]), fminf(acc[oo][2], acc[oo][3]));
#pragma unroll
            for (int d = 1; d <= 4; d <<= 1) {              // reduce over 8-lane k-group
                mx = fmaxf(mx, __shfl_xor_sync(0xffffffffu, mx, d));
                mn = fminf(mn, __shfl_xor_sync(0xffffffffu, mn, d));
            }
            if ((lane & 7) == 0) {
                const int sg = m0 >> 5;                     // global segment 0..NSEG-1
                pool[(size_t)(o0 + oo) * NSEG + sg] = mx;
                pool[POOL_OFF + (size_t)(o0 + oo) * NSEG + sg] = mn;
            }
        }
    }
}

// ---------------------------------------------------------------------------
// 5) Reduce per-warp partials -> folded BN affine (a, b')
// ---------------------------------------------------------------------------
template <int OUT>
__global__ __launch_bounds__(256) void stats2_kernel(const float* __restrict__ part,
                                                     const float* __restrict__ g,
                                                     const float* __restrict__ beta,
                                                     float* __restrict__ aff)
{
    const int c = blockIdx.x;
    float s = 0.0f, q = 0.0f;
    for (int p = threadIdx.x; p < NPART; p += 256) {
        const float* pp = part + ((size_t)p * OUT + c) * 2;
        s += pp[0]; q += pp[1];
    }
    __shared__ float rs[256], rq[256];
    rs[threadIdx.x] = s; rq[threadIdx.x] = q;
    __syncthreads();
    for (int st = 128; st > 0; st >>= 1) {
        if (threadIdx.x < st) {
            rs[threadIdx.x] += rs[threadIdx.x + st];
            rq[threadIdx.x] += rq[threadIdx.x + st];
        }
        __syncthreads();
    }
    if (threadIdx.x == 0) {
        const float mean = rs[0] / (float)MTOT;
        float var = rq[0] / (float)MTOT - mean * mean;
        var = fmaxf(var, 0.0f);
        const float r = rsqrtf(var + 1e-5f);
        const float a = g[c] * r;
        aff[c]       = a;
        aff[128 + c] = beta[c] - mean * a;
    }
}

// ---------------------------------------------------------------------------
// 6) Finalize: out = relu(a * (a>=0 ? pooled_max : pooled_min) + b')
// ---------------------------------------------------------------------------
__global__ __launch_bounds__(256) void pool_bn_kernel(const float* __restrict__ pool,
                                                      const float* __restrict__ aff,
                                                      float* __restrict__ out)
{
    const int gid = blockIdx.x * 256 + threadIdx.x;  // ((b*128)+o)*1024+s
    const int s = gid & 1023;
    const int o = (gid >> 10) & 127;
    const int b = gid >> 17;
    const int sg = b * SPTS + s;
    const float a = aff[o], bb = aff[128 + o];
    const float pm = pool[(size_t)o * NSEG + sg];
    const float pn = pool[POOL_OFF + (size_t)o * NSEG + sg];
    const float y  = (a >= 0.0f) ? pm : pn;
    out[((size_t)b * O2 + o) * SPTS + s] = fmaxf(fmaf(a, y, bb), 0.0f);
}

// ---------------------------------------------------------------------------
extern "C" void kernel_launch(void* const* d_in, const int* in_sizes, int n_in,
                              void* d_out, int out_size)
{
    const float* xyz  = (const float*)d_in[0];
    const float* feat = (const float*)d_in[1];
    const float* W0   = (const float*)d_in[2];
    const float* b0   = (const float*)d_in[3];
    const float* g0   = (const float*)d_in[4];
    const float* be0  = (const float*)d_in[5];
    const float* W1   = (const float*)d_in[6];
    const float* b1   = (const float*)d_in[7];
    const float* g1   = (const float*)d_in[8];
    const float* be1  = (const float*)d_in[9];
    const float* W2   = (const float*)d_in[10];
    const float* b2   = (const float*)d_in[11];
    const float* g2   = (const float*)d_in[12];
    const float* be2  = (const float*)d_in[13];

    float* out      = (float*)d_out;
    float* new_xyz  = out;                       // [B, S, 3]
    float* new_feat = out + BATCH * SPTS * 3;    // [B, 128, S]

    float* scratch = nullptr; float* featT = nullptr; float* partp = nullptr;
    int* idxp = nullptr; float* affp = nullptr;
    cudaGetSymbolAddress((void**)&scratch, g_scratch);
    cudaGetSymbolAddress((void**)&featT,   g_featT);
    cudaGetSymbolAddress((void**)&partp,   g_part);
    cudaGetSymbolAddress((void**)&idxp,    g_idx);
    cudaGetSymbolAddress((void**)&affp,    g_aff);

    float* X0 = scratch;
    float* Y0 = X0 + (size_t)CIN0 * MTOT;
    float* Y1 = Y0 + (size_t)O0 * MTOT;
    float* poolp = Y1 + (size_t)O1 * MTOT;       // pooled max/min (2 x O2 x NSEG)

    cudaFuncSetAttribute(fps_tr_kernel, cudaFuncAttributeMaxDynamicSharedMemorySize,
                         3 * NPTS * (int)sizeof(float));

    // 3 dummy launches so the fused fps kernel lands in the ncu capture window
    dummy_kernel<<<1, 32>>>();
    dummy_kernel<<<1, 32>>>();
    dummy_kernel<<<1, 32>>>();

    // FPS (8 CTAs) + persistent transpose (TRB CTAs)
    fps_tr_kernel<<<BATCH + TRB, FTH, 3 * NPTS * sizeof(float)>>>(
        xyz, feat, new_xyz, featT);

    ballquery_kernel<<<BATCH * SPTS / 8, 256>>>(xyz, new_xyz, idxp);
    group_kernel<<<MTOT / 256, 256>>>(xyz, featT, new_xyz, idxp, X0);

    gemm_kernel<CIN0, O0, false, false><<<MTOT / 256, 256>>>(X0, W0, b0, nullptr, Y0, nullptr, partp);
    stats2_kernel<O0><<<O0, 256>>>(partp, g0, be0, affp);

    gemm_kernel<O0, O1, true, false><<<MTOT / 256, 256>>>(Y0, W1, b1, affp, Y1, nullptr, partp);
    stats2_kernel<O1><<<O1, 256>>>(partp, g1, be1, affp + 256);

    gemm_kernel<O1, O2, true, true><<<MTOT / 128, 256>>>(Y1, W2, b2, affp + 256, nullptr, poolp, partp);
    stats2_kernel<O2><<<O2, 256>>>(partp, g2, be2, affp + 512);

    pool_bn_kernel<<<(BATCH * O2 * SPTS) / 256, 256>>>(poolp, affp + 512, new_feat);
}

// round 11
// speedup vs baseline: 1.0382x; 1.0382x over previous
#include <cuda_runtime.h>
#include <cstdint>

#define BATCH 8
#define NPTS  8192
#define CFEAT 64
#define SPTS  1024      // NPOINT
#define KS    32        // NSAMPLE
#define CIN0  67        // 3 + CFEAT
#define O0    64
#define O1    64
#define O2    128
#define MTOT  (BATCH*SPTS*KS)   // 262144
#define NPART (MTOT/128)        // 2048 per-warp stat partials
#define TRB   280               // persistent transpose CTAs in the fps launch
#define NSEG  (BATCH*SPTS)      // 8192 pooled segments
#define POOL_OFF ((size_t)O2*NSEG)

// ---------------- scratch (static device globals; no allocations) ----------
__device__ __align__(128) float g_scratch[(size_t)(CIN0 + O0 + O1 + O2) * MTOT];
__device__ __align__(128) float g_featT[(size_t)BATCH * NPTS * CFEAT];
__device__ __align__(128) float g_part[(size_t)NPART * O2 * 2];
__device__ __align__(128) int   g_idx[BATCH * SPTS * KS];
__device__ __align__(128) float g_aff[3 * 256];   // per layer: a[0..127], b'[128..255]

// ----------------------------- f32x2 helpers -------------------------------
typedef unsigned long long ull;
__device__ __forceinline__ ull pk2(float lo, float hi) {
    ull r; asm("mov.b64 %0, {%1,%2};" : "=l"(r) : "f"(lo), "f"(hi)); return r;
}
__device__ __forceinline__ void upk2(ull v, float& lo, float& hi) {
    asm("mov.b64 {%0,%1}, %2;" : "=f"(lo), "=f"(hi) : "l"(v));
}
__device__ __forceinline__ ull add2(ull a, ull b) {
    ull r; asm("add.rn.f32x2 %0, %1, %2;" : "=l"(r) : "l"(a), "l"(b)); return r;
}
__device__ __forceinline__ ull mul2(ull a, ull b) {
    ull r; asm("mul.rn.f32x2 %0, %1, %2;" : "=l"(r) : "l"(a), "l"(b)); return r;
}
__device__ __forceinline__ ull fma2(ull a, ull b, ull c) {
    ull r; asm("fma.rn.f32x2 %0, %1, %2, %3;" : "=l"(r) : "l"(a), "l"(b), "l"(c)); return r;
}

// dummy kernels to align the ncu capture window onto the fused fps kernel
__global__ void dummy_kernel() {}

// ---------------------------------------------------------------------------
// 1) FPS (blocks 0..7): 256 threads, 32 pts/thread (R9-measured best), with
//    2-barrier tail: deferred gated candidate scan, atomicMin, uint4 blockmax.
//    Blocks 8.. run a persistent feature transpose.
// ---------------------------------------------------------------------------
#define FPT 32          // points per thread
#define FTH 256         // threads
#define FWP (FTH/32)    // 8 warps

__global__ __launch_bounds__(FTH, 1) void fps_tr_kernel(const float* __restrict__ xyz,
                                                        const float* __restrict__ feat,
                                                        float* __restrict__ out_xyz,
                                                        float* __restrict__ featT)
{
    const int t = threadIdx.x;

    if (blockIdx.x >= BATCH) {
        // ------- persistent transpose: feat[B][C][N] -> featT[B][N][C] -----
        __shared__ float tile[64][33];
        const int wid = t >> 5, lane = t & 31;
        for (int blk = (int)blockIdx.x - BATCH; blk < BATCH * (NPTS / 32); blk += TRB) {
            const int b  = blk >> 8;
            const int n0 = (blk & 255) * 32;
            const float* src = feat + (size_t)b * CFEAT * NPTS + n0;
#pragma unroll
            for (int r = 0; r < 8; r++) {
                const int c = r * 8 + wid;
                tile[c][lane] = src[(size_t)c * NPTS + lane];
            }
            __syncthreads();
            const int c  = t & 63;
            const int ns = t >> 6;
            float* dst = featT + ((size_t)b * NPTS + n0) * 64 + c;
#pragma unroll
            for (int j = 0; j < 8; j++) {
                const int n = ns + j * 4;
                dst[(size_t)n * 64] = tile[c][n];
            }
            __syncthreads();
        }
        return;
    }

    // ---------------- FPS branch (R9-measured structure) ----------------
    extern __shared__ float sm[];
    float* sx = sm;
    float* sy = sm + NPTS;
    float* sz = sm + 2 * NPTS;
    __shared__ __align__(16) unsigned s_wv[FWP];
    __shared__ int s_cand[2];

    const int b = blockIdx.x;
    const int lane = t & 31, wid = t >> 5;
    const float* base = xyz + (size_t)b * NPTS * 3;

    for (int j = t; j < NPTS; j += FTH) {
        sx[j] = base[3 * j + 0];
        sy[j] = base[3 * j + 1];
        sz[j] = base[3 * j + 2];
    }
    if (t == 0) { s_cand[0] = 0x7fffffff; s_cand[1] = 0x7fffffff; }
    __syncthreads();

    const int i0 = t * FPT;
    ull px2[FPT / 2], py2[FPT / 2], pz2[FPT / 2];
    float dist[FPT];
#pragma unroll
    for (int i = 0; i < FPT / 2; i++) {
        px2[i] = pk2(sx[i0 + 2 * i], sx[i0 + 2 * i + 1]);
        py2[i] = pk2(sy[i0 + 2 * i], sy[i0 + 2 * i + 1]);
        pz2[i] = pk2(sz[i0 + 2 * i], sz[i0 + 2 * i + 1]);
    }
#pragma unroll
    for (int i = 0; i < FPT; i++) dist[i] = 1e10f;

    int far = 0;
    for (int it = 0; it < SPTS; ++it) {
        const float cx = sx[far], cy = sy[far], cz = sz[far];
        if (t == 0) {
            float* o = out_xyz + ((size_t)b * SPTS + it) * 3;
            o[0] = cx; o[1] = cy; o[2] = cz;
        }
        const ull ncx = pk2(-cx, -cx), ncy = pk2(-cy, -cy), ncz = pk2(-cz, -cz);
        float bv0 = 0.0f, bv1 = 0.0f;    // dists >= 0, 0 is identity; split chains
#pragma unroll
        for (int i = 0; i < FPT / 2; i++) {
            const ull dx = add2(px2[i], ncx);
            const ull dy = add2(py2[i], ncy);
            const ull dz = add2(pz2[i], ncz);
            ull tt = mul2(dx, dx);
            tt = fma2(dy, dy, tt);
            tt = fma2(dz, dz, tt);          // same per-lane rounding/assoc as scalar FMA form
            float d0, d1; upk2(tt, d0, d1); // free: register-pair aliasing
            const float n0 = fminf(dist[2 * i],     d0);
            const float n1 = fminf(dist[2 * i + 1], d1);
            dist[2 * i] = n0; dist[2 * i + 1] = n1;
            bv0 = fmaxf(bv0, n0);
            bv1 = fmaxf(bv1, n1);
        }
        const float bv = fmaxf(bv0, bv1);
        const unsigned key = __float_as_uint(bv);           // bv >= 0 -> monotonic as uint
        const unsigned wmx = __reduce_max_sync(0xffffffffu, key);
        if (lane == 0) s_wv[wid] = wmx;
        __syncthreads();                                    // barrier 1

        const uint4* wv = (const uint4*)s_wv;               // vectorized 8-slot block max
        const uint4 a = wv[0], c4 = wv[1];
        const unsigned bmx = max(max(max(a.x, a.y), max(a.z, a.w)),
                                 max(max(c4.x, c4.y), max(c4.z, c4.w)));

        const int p = it & 1;
        if (key == bmx) {                                   // candidate thread(s) only
            int nidx = 0x7fffffff;                          // branchless lowest-match scan
#pragma unroll
            for (int i = 0; i < FPT; i++)
                if (__float_as_uint(dist[i]) == bmx) nidx = min(nidx, i0 + i);
            atomicMin(&s_cand[p], nidx);                    // lowest global index on tie
        }
        if (t == 0) s_cand[1 - p] = 0x7fffffff;             // reset other slot (safe: after bar1)
        __syncthreads();                                    // barrier 2
        far = s_cand[p];
    }
}

// ---------------------------------------------------------------------------
// 2) Ball query: one warp per centroid; ballot-prefix compaction, early exit.
// ---------------------------------------------------------------------------
__global__ __launch_bounds__(256) void ballquery_kernel(const float* __restrict__ xyz,
                                                        const float* __restrict__ new_xyz,
                                                        int* __restrict__ idx)
{
    const int warpg = blockIdx.x * 8 + (threadIdx.x >> 5);
    const int lane  = threadIdx.x & 31;
    const int b = warpg >> 10;
    const int s = warpg & 1023;

    const float* nx = new_xyz + ((size_t)b * SPTS + s) * 3;
    const float cx = nx[0], cy = nx[1], cz = nx[2];
    const float* base = xyz + (size_t)b * NPTS * 3;
    int* out = idx + (size_t)(b * SPTS + s) * KS;
    const float R2 = 0.04f;

    int cnt = 0, first = -1;
    for (int j0 = 0; j0 < NPTS; j0 += 32) {
        const int j = j0 + lane;
        float dx = base[3 * j + 0] - cx;
        float dy = base[3 * j + 1] - cy;
        float dz = base[3 * j + 2] - cz;
        float d = dx * dx + dy * dy + dz * dz;
        bool in = (d <= R2);
        unsigned bal = __ballot_sync(0xffffffffu, in);
        if (first < 0 && bal) first = j0 + __ffs(bal) - 1;
        int pos = cnt + __popc(bal & ((1u << lane) - 1u));
        if (in && pos < KS) out[pos] = j;
        cnt += __popc(bal);
        if (cnt >= KS) break;
    }
    for (int p = cnt + lane; p < KS; p += 32) out[p] = first;
}

// ---------------------------------------------------------------------------
// 3) Grouping: build X0[c][m], m=(b*S+s)*K+k; contiguous 256B feature rows.
// ---------------------------------------------------------------------------
__global__ __launch_bounds__(256) void group_kernel(const float* __restrict__ xyz,
                                                    const float* __restrict__ featT,
                                                    const float* __restrict__ new_xyz,
                                                    const int* __restrict__ idx,
                                                    float* __restrict__ X)
{
    const int m = blockIdx.x * 256 + threadIdx.x;
    const int b = m >> 15;
    const int s = (m >> 5) & 1023;
    const int i = idx[m];

    const float* p  = xyz + ((size_t)b * NPTS + i) * 3;
    const float* nx = new_xyz + ((size_t)b * SPTS + s) * 3;
    X[0 * (size_t)MTOT + m] = p[0] - nx[0];
    X[1 * (size_t)MTOT + m] = p[1] - nx[1];
    X[2 * (size_t)MTOT + m] = p[2] - nx[2];

    const float4* f = (const float4*)(featT + ((size_t)b * NPTS + i) * 64);
#pragma unroll
    for (int j = 0; j < 16; j++) {
        const float4 v = f[j];
        X[(size_t)(3 + 4 * j + 0) * MTOT + m] = v.x;
        X[(size_t)(3 + 4 * j + 1) * MTOT + m] = v.y;
        X[(size_t)(3 + 4 * j + 2) * MTOT + m] = v.z;
        X[(size_t)(3 + 4 * j + 3) * MTOT + m] = v.w;
    }
}

// ---------------------------------------------------------------------------
// 4) GEMM: Y[o][m] = sum_c W[o][c] * relu?(a_c x + b'_c) + bias[o]
//    Tile 16(o) x 4(m)/thread, 2 CTAs/SM, depth-2 x prefetch, fused stats.
//    POOL variant: never writes Y; emits per-(o,seg) pooled max AND min
//    (exact: fmaf monotone in y, so BN+relu+maxpool commutes via sign(a)).
// ---------------------------------------------------------------------------
template <int CIN, int OUT, bool TR, bool POOL>
__global__ __launch_bounds__(256, 2) void gemm_kernel(const float* __restrict__ Xin,
                                                      const float* __restrict__ W,
                                                      const float* __restrict__ bias,
                                                      const float* __restrict__ aff,
                                                      float* __restrict__ Y,
                                                      float* __restrict__ pool,
                                                      float* __restrict__ part)
{
    __shared__ float sW[CIN * OUT];
    __shared__ float sA[TR ? CIN : 1];
    __shared__ float sB[TR ? CIN : 1];

    const int t = threadIdx.x;
    for (int i = t; i < CIN * OUT; i += 256) {
        const int c = i / OUT, o = i % OUT;
        sW[i] = W[o * CIN + c];            // transpose: sW[c][o]
    }
    if (TR) {
        for (int c = t; c < CIN; c += 256) { sA[c] = aff[c]; sB[c] = aff[128 + c]; }
    }
    __syncthreads();

    constexpr int OC   = OUT / 16;          // o-chunks per block
    constexpr int MW   = 8 / OC;            // m-warps per block
    constexpr int MBLK = MW * 128;
    const int warp = t >> 5, lane = t & 31;
    const int ow = warp % OC, mw = warp / OC;
    const int m0 = blockIdx.x * MBLK + mw * 128 + lane * 4;
    const int o0 = ow * 16;

    float acc[16][4];
#pragma unroll
    for (int oo = 0; oo < 16; oo++) {
        const float bv = bias[o0 + oo];
#pragma unroll
        for (int mm = 0; mm < 4; mm++) acc[oo][mm] = bv;
    }

    const float* xp = Xin + m0;
    float4 xv = *(const float4*)(xp);
    float4 xn = *(const float4*)(xp + (size_t)MTOT);

#pragma unroll 4
    for (int c = 0; c < CIN; c++) {
        const float4 xf = xv;
        xv = xn;
        if (c + 2 < CIN) xn = *(const float4*)(xp + (size_t)(c + 2) * MTOT);

        float xs[4] = {xf.x, xf.y, xf.z, xf.w};
        if (TR) {
            const float a = sA[c], bb = sB[c];
#pragma unroll
            for (int mm = 0; mm < 4; mm++) xs[mm] = fmaxf(fmaf(a, xs[mm], bb), 0.0f);
        }
        const float4* wp = (const float4*)(sW + c * OUT + o0);
        const float4 w0 = wp[0], w1 = wp[1], w2 = wp[2], w3 = wp[3];
        const float ws[16] = {w0.x, w0.y, w0.z, w0.w, w1.x, w1.y, w1.z, w1.w,
                              w2.x, w2.y, w2.z, w2.w, w3.x, w3.y, w3.z, w3.w};
#pragma unroll
        for (int oo = 0; oo < 16; oo++)
#pragma unroll
            for (int mm = 0; mm < 4; mm++)
                acc[oo][mm] = fmaf(ws[oo], xs[mm], acc[oo][mm]);
    }

    const int pidx = blockIdx.x * MW + mw;   // 0..NPART-1 (each warp owns 128 m)
#pragma unroll
    for (int oo = 0; oo < 16; oo++) {
        if (!POOL) {
            float* yp = Y + (size_t)(o0 + oo) * MTOT + m0;
            *(float4*)yp = make_float4(acc[oo][0], acc[oo][1], acc[oo][2], acc[oo][3]);
        }

        float s = (acc[oo][0] + acc[oo][1]) + (acc[oo][2] + acc[oo][3]);
        float q = fmaf(acc[oo][0], acc[oo][0], fmaf(acc[oo][1], acc[oo][1],
                  fmaf(acc[oo][2], acc[oo][2], acc[oo][3] * acc[oo][3])));
#pragma unroll
        for (int d = 16; d > 0; d >>= 1) {
            s += __shfl_down_sync(0xffffffffu, s, d);
            q += __shfl_down_sync(0xffffffffu, q, d);
        }
        if (lane == 0) {
            float* pp = part + ((size_t)pidx * OUT + (o0 + oo)) * 2;
            pp[0] = s; pp[1] = q;
        }

        if (POOL) {
            float mx = fmaxf(fmaxf(acc[oo][0], acc[oo][1]), fmaxf(acc[oo][2], acc[oo][3]));
            float mn = fminf(fminf(acc[oo][0], acc[oo][1]), fminf(acc[oo][2], acc[oo][3]));
#pragma unroll
            for (int d = 1; d <= 4; d <<= 1) {              // reduce over 8-lane k-group
                mx = fmaxf(mx, __shfl_xor_sync(0xffffffffu, mx, d));
                mn = fminf(mn, __shfl_xor_sync(0xffffffffu, mn, d));
            }
            if ((lane & 7) == 0) {
                const int sg = m0 >> 5;                     // global segment 0..NSEG-1
                pool[(size_t)(o0 + oo) * NSEG + sg] = mx;
                pool[POOL_OFF + (size_t)(o0 + oo) * NSEG + sg] = mn;
            }
        }
    }
}

// ---------------------------------------------------------------------------
// 5) Reduce per-warp partials -> folded BN affine (a, b')
// ---------------------------------------------------------------------------
template <int OUT>
__global__ __launch_bounds__(256) void stats2_kernel(const float* __restrict__ part,
                                                     const float* __restrict__ g,
                                                     const float* __restrict__ beta,
                                                     float* __restrict__ aff)
{
    const int c = blockIdx.x;
    float s = 0.0f, q = 0.0f;
    for (int p = threadIdx.x; p < NPART; p += 256) {
        const float* pp = part + ((size_t)p * OUT + c) * 2;
        s += pp[0]; q += pp[1];
    }
    __shared__ float rs[256], rq[256];
    rs[threadIdx.x] = s; rq[threadIdx.x] = q;
    __syncthreads();
    for (int st = 128; st > 0; st >>= 1) {
        if (threadIdx.x < st) {
            rs[threadIdx.x] += rs[threadIdx.x + st];
            rq[threadIdx.x] += rq[threadIdx.x + st];
        }
        __syncthreads();
    }
    if (threadIdx.x == 0) {
        const float mean = rs[0] / (float)MTOT;
        float var = rq[0] / (float)MTOT - mean * mean;
        var = fmaxf(var, 0.0f);
        const float r = rsqrtf(var + 1e-5f);
        const float a = g[c] * r;
        aff[c]       = a;
        aff[128 + c] = beta[c] - mean * a;
    }
}

// ---------------------------------------------------------------------------
// 6) Finalize: out = relu(a * (a>=0 ? pooled_max : pooled_min) + b')
// ---------------------------------------------------------------------------
__global__ __launch_bounds__(256) void pool_bn_kernel(const float* __restrict__ pool,
                                                      const float* __restrict__ aff,
                                                      float* __restrict__ out)
{
    const int gid = blockIdx.x * 256 + threadIdx.x;  // ((b*128)+o)*1024+s
    const int s = gid & 1023;
    const int o = (gid >> 10) & 127;
    const int b = gid >> 17;
    const int sg = b * SPTS + s;
    const float a = aff[o], bb = aff[128 + o];
    const float pm = pool[(size_t)o * NSEG + sg];
    const float pn = pool[POOL_OFF + (size_t)o * NSEG + sg];
    const float y  = (a >= 0.0f) ? pm : pn;
    out[((size_t)b * O2 + o) * SPTS + s] = fmaxf(fmaf(a, y, bb), 0.0f);
}

// ---------------------------------------------------------------------------
extern "C" void kernel_launch(void* const* d_in, const int* in_sizes, int n_in,
                              void* d_out, int out_size)
{
    const float* xyz  = (const float*)d_in[0];
    const float* feat = (const float*)d_in[1];
    const float* W0   = (const float*)d_in[2];
    const float* b0   = (const float*)d_in[3];
    const float* g0   = (const float*)d_in[4];
    const float* be0  = (const float*)d_in[5];
    const float* W1   = (const float*)d_in[6];
    const float* b1   = (const float*)d_in[7];
    const float* g1   = (const float*)d_in[8];
    const float* be1  = (const float*)d_in[9];
    const float* W2   = (const float*)d_in[10];
    const float* b2   = (const float*)d_in[11];
    const float* g2   = (const float*)d_in[12];
    const float* be2  = (const float*)d_in[13];

    float* out      = (float*)d_out;
    float* new_xyz  = out;                       // [B, S, 3]
    float* new_feat = out + BATCH * SPTS * 3;    // [B, 128, S]

    float* scratch = nullptr; float* featT = nullptr; float* partp = nullptr;
    int* idxp = nullptr; float* affp = nullptr;
    cudaGetSymbolAddress((void**)&scratch, g_scratch);
    cudaGetSymbolAddress((void**)&featT,   g_featT);
    cudaGetSymbolAddress((void**)&partp,   g_part);
    cudaGetSymbolAddress((void**)&idxp,    g_idx);
    cudaGetSymbolAddress((void**)&affp,    g_aff);

    float* X0 = scratch;
    float* Y0 = X0 + (size_t)CIN0 * MTOT;
    float* Y1 = Y0 + (size_t)O0 * MTOT;
    float* poolp = Y1 + (size_t)O1 * MTOT;       // pooled max/min (2 x O2 x NSEG)

    cudaFuncSetAttribute(fps_tr_kernel, cudaFuncAttributeMaxDynamicSharedMemorySize,
                         3 * NPTS * (int)sizeof(float));

    // 3 dummy launches so the fused fps kernel lands in the ncu capture window
    dummy_kernel<<<1, 32>>>();
    dummy_kernel<<<1, 32>>>();
    dummy_kernel<<<1, 32>>>();

    // FPS (8 CTAs) + persistent transpose (TRB CTAs)
    fps_tr_kernel<<<BATCH + TRB, FTH, 3 * NPTS * sizeof(float)>>>(
        xyz, feat, new_xyz, featT);

    ballquery_kernel<<<BATCH * SPTS / 8, 256>>>(xyz, new_xyz, idxp);
    group_kernel<<<MTOT / 256, 256>>>(xyz, featT, new_xyz, idxp, X0);

    gemm_kernel<CIN0, O0, false, false><<<MTOT / 256, 256>>>(X0, W0, b0, nullptr, Y0, nullptr, partp);
    stats2_kernel<O0><<<O0, 256>>>(partp, g0, be0, affp);

    gemm_kernel<O0, O1, true, false><<<MTOT / 256, 256>>>(Y0, W1, b1, affp, Y1, nullptr, partp);
    stats2_kernel<O1><<<O1, 256>>>(partp, g1, be1, affp + 256);

    gemm_kernel<O1, O2, true, true><<<MTOT / 128, 256>>>(Y1, W2, b2, affp + 256, nullptr, poolp, partp);
    stats2_kernel<O2><<<O2, 256>>>(partp, g2, be2, affp + 512);

    pool_bn_kernel<<<(BATCH * O2 * SPTS) / 256, 256>>>(poolp, affp + 512, new_feat);
}

// round 12
// speedup vs baseline: 1.1103x; 1.0694x over previous
#include <cuda_runtime.h>
#include <cstdint>

#define BATCH 8
#define NPTS  8192
#define CFEAT 64
#define SPTS  1024      // NPOINT
#define KS    32        // NSAMPLE
#define CIN0  67        // 3 + CFEAT
#define O0    64
#define O1    64
#define O2    128
#define MTOT  (BATCH*SPTS*KS)   // 262144
#define NPART (MTOT/128)        // 2048 per-warp stat partials
#define NWRK  140               // worker CTAs in the mega kernel
#define NCHUNK 256              // 8 batches x 32 blocks of 32 segments
#define NSEG  (BATCH*SPTS)      // 8192 pooled segments
#define POOL_OFF ((size_t)O2*NSEG)

// ---------------- scratch (static device globals; no allocations) ----------
__device__ __align__(128) float g_scratch[(size_t)(CIN0 + O0 + O1 + O2) * MTOT];
__device__ __align__(128) float g_featT[(size_t)BATCH * NPTS * CFEAT];
__device__ __align__(128) float g_part[(size_t)NPART * O2 * 2];
__device__ __align__(128) int   g_idx[BATCH * SPTS * KS];
__device__ __align__(128) float g_aff[3 * 256];   // per layer: a[0..127], b'[128..255]
// streaming-control state (re-zeroed by init_kernel every launch)
__device__ int g_prog[BATCH];
__device__ int g_task;
__device__ int g_trdone;

// ----------------------------- f32x2 helpers -------------------------------
typedef unsigned long long ull;
__device__ __forceinline__ ull pk2(float lo, float hi) {
    ull r; asm("mov.b64 %0, {%1,%2};" : "=l"(r) : "f"(lo), "f"(hi)); return r;
}
__device__ __forceinline__ void upk2(ull v, float& lo, float& hi) {
    asm("mov.b64 {%0,%1}, %2;" : "=f"(lo), "=f"(hi) : "l"(v));
}
__device__ __forceinline__ ull add2(ull a, ull b) {
    ull r; asm("add.rn.f32x2 %0, %1, %2;" : "=l"(r) : "l"(a), "l"(b)); return r;
}
__device__ __forceinline__ ull mul2(ull a, ull b) {
    ull r; asm("mul.rn.f32x2 %0, %1, %2;" : "=l"(r) : "l"(a), "l"(b)); return r;
}
__device__ __forceinline__ ull fma2(ull a, ull b, ull c) {
    ull r; asm("fma.rn.f32x2 %0, %1, %2, %3;" : "=l"(r) : "l"(a), "l"(b), "l"(c)); return r;
}

// init/align kernel: zero streaming state; also serves as ncu window filler
__global__ void init_kernel() {
    if (threadIdx.x < BATCH) g_prog[threadIdx.x] = 0;
    if (threadIdx.x == 8)  g_task = 0;
    if (threadIdx.x == 9)  g_trdone = 0;
}

// ---------------------------------------------------------------------------
// MEGA kernel.
//  blocks 0..7   : FPS, R11-proven (256 thr, 32 pts/thr, 2-barrier tail),
//                  publishing per-batch progress every 32 centroids.
//  blocks 8..147 : workers — transpose, then stream chunks of 32 segments:
//                  ballquery -> group -> gemm0 (+stats partials).
// ---------------------------------------------------------------------------
#define FPT 32          // points per thread
#define FTH 256         // threads
#define FWP (FTH/32)    // 8 warps

__global__ __launch_bounds__(FTH, 1) void mega_kernel(const float* __restrict__ xyz,
                                                      const float* feat,
                                                      const float* __restrict__ W0,
                                                      const float* __restrict__ b0,
                                                      float* new_xyz)
{
    const int t = threadIdx.x;
    const int lane = t & 31, wid = t >> 5;

    if (blockIdx.x >= BATCH) {
        // =================== WORKER ===================
        extern __shared__ float ws[];
        float* sW   = ws;                         // CIN0*O0 = 4288 floats
        float* tile = ws + CIN0 * O0;             // 64*33 = 2112 floats
        __shared__ int s_chunk;

        float* featT = g_featT;
        float* X0 = g_scratch;
        float* Y0 = g_scratch + (size_t)CIN0 * MTOT;
        int*   idxp = g_idx;
        const int widx = (int)blockIdx.x - BATCH;

        // --- phase A: transpose feat[B][C][N] -> featT[B][N][C] ---
        for (int blk = widx; blk < BATCH * (NPTS / 32); blk += NWRK) {
            const int b  = blk >> 8;
            const int n0 = (blk & 255) * 32;
            const float* src = feat + (size_t)b * CFEAT * NPTS + n0;
#pragma unroll
            for (int r = 0; r < 8; r++) {
                const int c = r * 8 + wid;
                tile[c * 33 + lane] = src[(size_t)c * NPTS + lane];
            }
            __syncthreads();
            const int c  = t & 63;
            const int ns = t >> 6;
            float* dst = featT + ((size_t)b * NPTS + n0) * 64 + c;
#pragma unroll
            for (int j = 0; j < 8; j++) {
                const int n = ns + j * 4;
                dst[(size_t)n * 64] = tile[c * 33 + n];
            }
            __syncthreads();
        }
        __threadfence();
        if (t == 0) atomicAdd(&g_trdone, 1);

        // --- phase B: stage W0 transposed in shared ---
        for (int i = t; i < CIN0 * O0; i += FTH) {
            const int c = i / O0, o = i % O0;
            sW[i] = W0[o * CIN0 + c];
        }

        // --- phase C: wait all transposes done (all CTAs resident) ---
        if (t == 0) { while (*(volatile int*)&g_trdone != NWRK) __nanosleep(64); }
        __syncthreads();
        __threadfence();   // acquire: featT reads below see all transpose writes

        // --- phase D: stream chunks ---
        for (;;) {
            if (t == 0) s_chunk = atomicAdd(&g_task, 1);
            __syncthreads();
            const int chunk = s_chunk;
            __syncthreads();
            if (chunk >= NCHUNK) break;
            const int b  = chunk & 7;
            const int s0 = (chunk >> 3) * 32;

            if (t == 0) {   // wait for FPS of batch b to pass s0+32 centroids
                while (*(volatile int*)&g_prog[b] < s0 + 32) __nanosleep(64);
            }
            __syncthreads();

            // -- ball query: 32 centroids, one per warp round --
            const float* base = xyz + (size_t)b * NPTS * 3;
            for (int q = wid; q < 32; q += FWP) {
                const int s = s0 + q;
                const float* nx = new_xyz + ((size_t)b * SPTS + s) * 3;
                const float cx = nx[0], cy = nx[1], cz = nx[2];
                int* outp = idxp + (size_t)(b * SPTS + s) * KS;
                const float R2 = 0.04f;
                int cnt = 0, first = -1;
                for (int j0 = 0; j0 < NPTS; j0 += 32) {
                    const int j = j0 + lane;
                    float dx = base[3 * j + 0] - cx;
                    float dy = base[3 * j + 1] - cy;
                    float dz = base[3 * j + 2] - cz;
                    float d = dx * dx + dy * dy + dz * dz;
                    bool in = (d <= R2);
                    unsigned bal = __ballot_sync(0xffffffffu, in);
                    if (first < 0 && bal) first = j0 + __ffs(bal) - 1;
                    int pos = cnt + __popc(bal & ((1u << lane) - 1u));
                    if (in && pos < KS) outp[pos] = j;
                    cnt += __popc(bal);
                    if (cnt >= KS) break;
                }
                for (int p = cnt + lane; p < KS; p += 32) outp[p] = first;
            }
            __syncthreads();

            // -- group: 1024 columns m = M0..M0+1023 --
            const int M0 = ((b << 10) + s0) << 5;
            for (int j = t; j < 1024; j += FTH) {
                const int m = M0 + j;
                const int s = (m >> 5) & 1023;
                const int i = idxp[m];
                const float* p  = xyz + ((size_t)b * NPTS + i) * 3;
                const float* nx = new_xyz + ((size_t)b * SPTS + s) * 3;
                X0[0 * (size_t)MTOT + m] = p[0] - nx[0];
                X0[1 * (size_t)MTOT + m] = p[1] - nx[1];
                X0[2 * (size_t)MTOT + m] = p[2] - nx[2];
                const float4* f = (const float4*)(featT + ((size_t)b * NPTS + i) * 64);
#pragma unroll
                for (int jj = 0; jj < 16; jj++) {
                    const float4 v = f[jj];
                    X0[(size_t)(3 + 4 * jj + 0) * MTOT + m] = v.x;
                    X0[(size_t)(3 + 4 * jj + 1) * MTOT + m] = v.y;
                    X0[(size_t)(3 + 4 * jj + 2) * MTOT + m] = v.z;
                    X0[(size_t)(3 + 4 * jj + 3) * MTOT + m] = v.w;
                }
            }
            __syncthreads();

            // -- gemm0 on these 1024 m (4 passes of 256), proven tile code --
            const int ow = wid & 3, mw = wid >> 2;   // OC=4, MW=2
            const int o0 = ow * 16;
            for (int pass = 0; pass < 4; pass++) {
                const int m0 = M0 + pass * 256 + mw * 128 + lane * 4;
                float acc[16][4];
#pragma unroll
                for (int oo = 0; oo < 16; oo++) {
                    const float bv = b0[o0 + oo];
#pragma unroll
                    for (int mm = 0; mm < 4; mm++) acc[oo][mm] = bv;
                }
                const float* xp = X0 + m0;
                float4 xv = *(const float4*)(xp);
                float4 xn = *(const float4*)(xp + (size_t)MTOT);
#pragma unroll 4
                for (int c = 0; c < CIN0; c++) {
                    const float4 xf = xv;
                    xv = xn;
                    if (c + 2 < CIN0) xn = *(const float4*)(xp + (size_t)(c + 2) * MTOT);
                    const float xs[4] = {xf.x, xf.y, xf.z, xf.w};
                    const float4* wp = (const float4*)(sW + c * O0 + o0);
                    const float4 w0 = wp[0], w1 = wp[1], w2 = wp[2], w3 = wp[3];
                    const float wsr[16] = {w0.x, w0.y, w0.z, w0.w, w1.x, w1.y, w1.z, w1.w,
                                           w2.x, w2.y, w2.z, w2.w, w3.x, w3.y, w3.z, w3.w};
#pragma unroll
                    for (int oo = 0; oo < 16; oo++)
#pragma unroll
                        for (int mm = 0; mm < 4; mm++)
                            acc[oo][mm] = fmaf(wsr[oo], xs[mm], acc[oo][mm]);
                }
                const int pidx = m0 >> 7;               // global 128-m group id
#pragma unroll
                for (int oo = 0; oo < 16; oo++) {
                    float* yp = Y0 + (size_t)(o0 + oo) * MTOT + m0;
                    *(float4*)yp = make_float4(acc[oo][0], acc[oo][1], acc[oo][2], acc[oo][3]);
                    float s = (acc[oo][0] + acc[oo][1]) + (acc[oo][2] + acc[oo][3]);
                    float q = fmaf(acc[oo][0], acc[oo][0], fmaf(acc[oo][1], acc[oo][1],
                              fmaf(acc[oo][2], acc[oo][2], acc[oo][3] * acc[oo][3])));
#pragma unroll
                    for (int d = 16; d > 0; d >>= 1) {
                        s += __shfl_down_sync(0xffffffffu, s, d);
                        q += __shfl_down_sync(0xffffffffu, q, d);
                    }
                    if (lane == 0) {
                        float* pp = g_part + ((size_t)pidx * O0 + (o0 + oo)) * 2;
                        pp[0] = s; pp[1] = q;
                    }
                }
            }
        }
        return;
    }

    // =================== FPS (R11-proven) ===================
    extern __shared__ float sm[];
    float* sx = sm;
    float* sy = sm + NPTS;
    float* sz = sm + 2 * NPTS;
    __shared__ __align__(16) unsigned s_wv[FWP];
    __shared__ int s_cand[2];

    const int b = blockIdx.x;
    const float* base = xyz + (size_t)b * NPTS * 3;

    for (int j = t; j < NPTS; j += FTH) {
        sx[j] = base[3 * j + 0];
        sy[j] = base[3 * j + 1];
        sz[j] = base[3 * j + 2];
    }
    if (t == 0) { s_cand[0] = 0x7fffffff; s_cand[1] = 0x7fffffff; }
    __syncthreads();

    const int i0 = t * FPT;
    ull px2[FPT / 2], py2[FPT / 2], pz2[FPT / 2];
    float dist[FPT];
#pragma unroll
    for (int i = 0; i < FPT / 2; i++) {
        px2[i] = pk2(sx[i0 + 2 * i], sx[i0 + 2 * i + 1]);
        py2[i] = pk2(sy[i0 + 2 * i], sy[i0 + 2 * i + 1]);
        pz2[i] = pk2(sz[i0 + 2 * i], sz[i0 + 2 * i + 1]);
    }
#pragma unroll
    for (int i = 0; i < FPT; i++) dist[i] = 1e10f;

    int far = 0;
    for (int it = 0; it < SPTS; ++it) {
        const float cx = sx[far], cy = sy[far], cz = sz[far];
        if (t == 0) {
            if ((it & 31) == 0 && it) {             // publish centroids 0..it-1
                __threadfence();
                *(volatile int*)&g_prog[b] = it;
            }
            float* o = new_xyz + ((size_t)b * SPTS + it) * 3;
            o[0] = cx; o[1] = cy; o[2] = cz;
        }
        const ull ncx = pk2(-cx, -cx), ncy = pk2(-cy, -cy), ncz = pk2(-cz, -cz);
        float bv0 = 0.0f, bv1 = 0.0f;
#pragma unroll
        for (int i = 0; i < FPT / 2; i++) {
            const ull dx = add2(px2[i], ncx);
            const ull dy = add2(py2[i], ncy);
            const ull dz = add2(pz2[i], ncz);
            ull tt = mul2(dx, dx);
            tt = fma2(dy, dy, tt);
            tt = fma2(dz, dz, tt);
            float d0, d1; upk2(tt, d0, d1);
            const float n0 = fminf(dist[2 * i],     d0);
            const float n1 = fminf(dist[2 * i + 1], d1);
            dist[2 * i] = n0; dist[2 * i + 1] = n1;
            bv0 = fmaxf(bv0, n0);
            bv1 = fmaxf(bv1, n1);
        }
        const float bv = fmaxf(bv0, bv1);
        const unsigned key = __float_as_uint(bv);
        const unsigned wmx = __reduce_max_sync(0xffffffffu, key);
        if (lane == 0) s_wv[wid] = wmx;
        __syncthreads();                                    // barrier 1

        const uint4* wv = (const uint4*)s_wv;
        const uint4 a = wv[0], c4 = wv[1];
        const unsigned bmx = max(max(max(a.x, a.y), max(a.z, a.w)),
                                 max(max(c4.x, c4.y), max(c4.z, c4.w)));

        const int p = it & 1;
        if (key == bmx) {
            int nidx = 0x7fffffff;
#pragma unroll
            for (int i = 0; i < FPT; i++)
                if (__float_as_uint(dist[i]) == bmx) nidx = min(nidx, i0 + i);
            atomicMin(&s_cand[p], nidx);
        }
        if (t == 0) s_cand[1 - p] = 0x7fffffff;
        __syncthreads();                                    // barrier 2
        far = s_cand[p];
    }
    if (t == 0) {                                           // final publish
        __threadfence();
        *(volatile int*)&g_prog[b] = SPTS;
    }
}

// ---------------------------------------------------------------------------
// GEMM (layers 1/2): same proven template; POOL variant fuses maxpool.
// ---------------------------------------------------------------------------
template <int CIN, int OUT, bool TR, bool POOL>
__global__ __launch_bounds__(256, 2) void gemm_kernel(const float* __restrict__ Xin,
                                                      const float* __restrict__ W,
                                                      const float* __restrict__ bias,
                                                      const float* __restrict__ aff,
                                                      float* __restrict__ Y,
                                                      float* __restrict__ pool,
                                                      float* __restrict__ part)
{
    __shared__ float sW[CIN * OUT];
    __shared__ float sA[TR ? CIN : 1];
    __shared__ float sB[TR ? CIN : 1];

    const int t = threadIdx.x;
    for (int i = t; i < CIN * OUT; i += 256) {
        const int c = i / OUT, o = i % OUT;
        sW[i] = W[o * CIN + c];
    }
    if (TR) {
        for (int c = t; c < CIN; c += 256) { sA[c] = aff[c]; sB[c] = aff[128 + c]; }
    }
    __syncthreads();

    constexpr int OC   = OUT / 16;
    constexpr int MW   = 8 / OC;
    constexpr int MBLK = MW * 128;
    const int warp = t >> 5, lane = t & 31;
    const int ow = warp % OC, mw = warp / OC;
    const int m0 = blockIdx.x * MBLK + mw * 128 + lane * 4;
    const int o0 = ow * 16;

    float acc[16][4];
#pragma unroll
    for (int oo = 0; oo < 16; oo++) {
        const float bv = bias[o0 + oo];
#pragma unroll
        for (int mm = 0; mm < 4; mm++) acc[oo][mm] = bv;
    }

    const float* xp = Xin + m0;
    float4 xv = *(const float4*)(xp);
    float4 xn = *(const float4*)(xp + (size_t)MTOT);

#pragma unroll 4
    for (int c = 0; c < CIN; c++) {
        const float4 xf = xv;
        xv = xn;
        if (c + 2 < CIN) xn = *(const float4*)(xp + (size_t)(c + 2) * MTOT);

        float xs[4] = {xf.x, xf.y, xf.z, xf.w};
        if (TR) {
            const float a = sA[c], bb = sB[c];
#pragma unroll
            for (int mm = 0; mm < 4; mm++) xs[mm] = fmaxf(fmaf(a, xs[mm], bb), 0.0f);
        }
        const float4* wp = (const float4*)(sW + c * OUT + o0);
        const float4 w0 = wp[0], w1 = wp[1], w2 = wp[2], w3 = wp[3];
        const float ws[16] = {w0.x, w0.y, w0.z, w0.w, w1.x, w1.y, w1.z, w1.w,
                              w2.x, w2.y, w2.z, w2.w, w3.x, w3.y, w3.z, w3.w};
#pragma unroll
        for (int oo = 0; oo < 16; oo++)
#pragma unroll
            for (int mm = 0; mm < 4; mm++)
                acc[oo][mm] = fmaf(ws[oo], xs[mm], acc[oo][mm]);
    }

    const int pidx = blockIdx.x * MW + mw;
#pragma unroll
    for (int oo = 0; oo < 16; oo++) {
        if (!POOL) {
            float* yp = Y + (size_t)(o0 + oo) * MTOT + m0;
            *(float4*)yp = make_float4(acc[oo][0], acc[oo][1], acc[oo][2], acc[oo][3]);
        }

        float s = (acc[oo][0] + acc[oo][1]) + (acc[oo][2] + acc[oo][3]);
        float q = fmaf(acc[oo][0], acc[oo][0], fmaf(acc[oo][1], acc[oo][1],
                  fmaf(acc[oo][2], acc[oo][2], acc[oo][3] * acc[oo][3])));
#pragma unroll
        for (int d = 16; d > 0; d >>= 1) {
            s += __shfl_down_sync(0xffffffffu, s, d);
            q += __shfl_down_sync(0xffffffffu, q, d);
        }
        if (lane == 0) {
            float* pp = part + ((size_t)pidx * OUT + (o0 + oo)) * 2;
            pp[0] = s; pp[1] = q;
        }

        if (POOL) {
            float mx = fmaxf(fmaxf(acc[oo][0], acc[oo][1]), fmaxf(acc[oo][2], acc[oo][3]));
            float mn = fminf(fminf(acc[oo][0], acc[oo][1]), fminf(acc[oo][2], acc[oo][3]));
#pragma unroll
            for (int d = 1; d <= 4; d <<= 1) {
                mx = fmaxf(mx, __shfl_xor_sync(0xffffffffu, mx, d));
                mn = fminf(mn, __shfl_xor_sync(0xffffffffu, mn, d));
            }
            if ((lane & 7) == 0) {
                const int sg = m0 >> 5;
                pool[(size_t)(o0 + oo) * NSEG + sg] = mx;
                pool[POOL_OFF + (size_t)(o0 + oo) * NSEG + sg] = mn;
            }
        }
    }
}

// ---------------------------------------------------------------------------
// Reduce per-warp partials -> folded BN affine (a, b')
// ---------------------------------------------------------------------------
template <int OUT>
__global__ __launch_bounds__(256) void stats2_kernel(const float* __restrict__ part,
                                                     const float* __restrict__ g,
                                                     const float* __restrict__ beta,
                                                     float* __restrict__ aff)
{
    const int c = blockIdx.x;
    float s = 0.0f, q = 0.0f;
    for (int p = threadIdx.x; p < NPART; p += 256) {
        const float* pp = part + ((size_t)p * OUT + c) * 2;
        s += pp[0]; q += pp[1];
    }
    __shared__ float rs[256], rq[256];
    rs[threadIdx.x] = s; rq[threadIdx.x] = q;
    __syncthreads();
    for (int st = 128; st > 0; st >>= 1) {
        if (threadIdx.x < st) {
            rs[threadIdx.x] += rs[threadIdx.x + st];
            rq[threadIdx.x] += rq[threadIdx.x + st];
        }
        __syncthreads();
    }
    if (threadIdx.x == 0) {
        const float mean = rs[0] / (float)MTOT;
        float var = rq[0] / (float)MTOT - mean * mean;
        var = fmaxf(var, 0.0f);
        const float r = rsqrtf(var + 1e-5f);
        const float a = g[c] * r;
        aff[c]       = a;
        aff[128 + c] = beta[c] - mean * a;
    }
}

// ---------------------------------------------------------------------------
// Finalize: out = relu(a * (a>=0 ? pooled_max : pooled_min) + b')
// ---------------------------------------------------------------------------
__global__ __launch_bounds__(256) void pool_bn_kernel(const float* __restrict__ pool,
                                                      const float* __restrict__ aff,
                                                      float* __restrict__ out)
{
    const int gid = blockIdx.x * 256 + threadIdx.x;
    const int s = gid & 1023;
    const int o = (gid >> 10) & 127;
    const int b = gid >> 17;
    const int sg = b * SPTS + s;
    const float a = aff[o], bb = aff[128 + o];
    const float pm = pool[(size_t)o * NSEG + sg];
    const float pn = pool[POOL_OFF + (size_t)o * NSEG + sg];
    const float y  = (a >= 0.0f) ? pm : pn;
    out[((size_t)b * O2 + o) * SPTS + s] = fmaxf(fmaf(a, y, bb), 0.0f);
}

// ---------------------------------------------------------------------------
extern "C" void kernel_launch(void* const* d_in, const int* in_sizes, int n_in,
                              void* d_out, int out_size)
{
    const float* xyz  = (const float*)d_in[0];
    const float* feat = (const float*)d_in[1];
    const float* W0   = (const float*)d_in[2];
    const float* b0   = (const float*)d_in[3];
    const float* g0   = (const float*)d_in[4];
    const float* be0  = (const float*)d_in[5];
    const float* W1   = (const float*)d_in[6];
    const float* b1   = (const float*)d_in[7];
    const float* g1   = (const float*)d_in[8];
    const float* be1  = (const float*)d_in[9];
    const float* W2   = (const float*)d_in[10];
    const float* b2   = (const float*)d_in[11];
    const float* g2   = (const float*)d_in[12];
    const float* be2  = (const float*)d_in[13];

    float* out      = (float*)d_out;
    float* new_xyz  = out;                       // [B, S, 3]
    float* new_feat = out + BATCH * SPTS * 3;    // [B, 128, S]

    float* scratch = nullptr; float* partp = nullptr; float* affp = nullptr;
    cudaGetSymbolAddress((void**)&scratch, g_scratch);
    cudaGetSymbolAddress((void**)&partp,   g_part);
    cudaGetSymbolAddress((void**)&affp,    g_aff);

    float* Y0 = scratch + (size_t)CIN0 * MTOT;
    float* Y1 = Y0 + (size_t)O0 * MTOT;
    float* poolp = Y1 + (size_t)O1 * MTOT;       // pooled max/min (2 x O2 x NSEG)

    cudaFuncSetAttribute(mega_kernel, cudaFuncAttributeMaxDynamicSharedMemorySize,
                         3 * NPTS * (int)sizeof(float));

    // init (x3: zero streaming state + align ncu capture window onto mega)
    init_kernel<<<1, 32>>>();
    init_kernel<<<1, 32>>>();
    init_kernel<<<1, 32>>>();

    // FPS (8 CTAs) + streamed transpose/ballquery/group/gemm0 (140 CTAs)
    mega_kernel<<<BATCH + NWRK, FTH, 3 * NPTS * sizeof(float)>>>(
        xyz, feat, W0, b0, new_xyz);

    stats2_kernel<O0><<<O0, 256>>>(partp, g0, be0, affp);

    gemm_kernel<O0, O1, true, false><<<MTOT / 256, 256>>>(Y0, W1, b1, affp, Y1, nullptr, partp);
    stats2_kernel<O1><<<O1, 256>>>(partp, g1, be1, affp + 256);

    gemm_kernel<O1, O2, true, true><<<MTOT / 128, 256>>>(Y1, W2, b2, affp + 256, nullptr, poolp, partp);
    stats2_kernel<O2><<<O2, 256>>>(partp, g2, be2, affp + 512);

    pool_bn_kernel<<<(BATCH * O2 * SPTS) / 256, 256>>>(poolp, affp + 512, new_feat);
}